// round 7
// baseline (speedup 1.0000x reference)
#include <cuda_runtime.h>
#include <cstddef>

#define B_  8
#define C_  64
#define N_  4096
#define N4_ 1024

// Scratch (static device globals).
__device__ float g_K [B_*C_*N_];   // (b,c,n)  keys   stage1, channel-major
__device__ float g_V [B_*N_*C_];   // (b,n,c)  values stage1, position-major
__device__ float g_Q [B_*C_*N_];   // (b,c,n)  queries stage2, channel-major
__device__ float g_qp[B_*C_*N4_];  // (b,c,j)  pooled queries stage1, channel-major
__device__ float g_o1[B_*N4_*C_];  // (b,j,c)  stage1 output, position-major
__device__ float g_kp[B_*C_*N4_];  // (b,c,j)  keys   stage2, channel-major
__device__ float g_vp[B_*N4_*C_];  // (b,j,c)  values stage2, position-major

typedef unsigned long long u64;

__device__ __forceinline__ u64 pack2(float x, float y) {
    u64 r; asm("mov.b64 %0, {%1,%2};" : "=l"(r) : "f"(x), "f"(y)); return r;
}
__device__ __forceinline__ float2 unpk(u64 v) {
    float2 r; asm("mov.b64 {%0,%1}, %2;" : "=f"(r.x), "=f"(r.y) : "l"(v)); return r;
}
__device__ __forceinline__ void fma2(u64& d, u64 a, u64 b) {
    asm("fma.rn.f32x2 %0, %1, %2, %0;" : "+l"(d) : "l"(a), "l"(b));
}
__device__ __forceinline__ void mul2(u64& d, u64 a) {
    asm("mul.rn.f32x2 %0, %0, %1;" : "+l"(d) : "l"(a));
}

union F4U { float4 v; float f[4]; u64 u[2]; };

// ================= Projection GEMM (64x64 W @ 64x64 X tile) ================
// 256 threads as 16x16: thread = 4 out-channels (ty) x 4 positions (tx),
// position pairs packed in f32x2. W^T duplicated in smem (pitch PW),
// X [k][p] (pitch PX). Per k-step: 3x LDS.128 + 8 FFMA2, no packing MOVs.
#define PW 136
#define PX 68
#define PROJ_SMEM_FLOATS (64*PW + 64*PX + 64)

__device__ __forceinline__ void load_w_dup(const float* __restrict__ w,
                                           const float* __restrict__ bias,
                                           float* sWTd, float* sb, int tid)
{
    for (int i = tid; i < 4096; i += 256) {
        int o = i >> 6, c = i & 63;
        float v = w[i];
        sWTd[c * PW + 2 * o]     = v;
        sWTd[c * PW + 2 * o + 1] = v;
    }
    if (tid < 64) sb[tid] = bias[tid];
}

__device__ __forceinline__ void gemm_tile(const float* sWTd, const float* sX,
                                          const float* sb, u64 acc2[4][2],
                                          int tx, int ty)
{
    #pragma unroll
    for (int i = 0; i < 4; i++) {
        float b = sb[4 * ty + i];
        u64 bb = pack2(b, b);
        acc2[i][0] = bb; acc2[i][1] = bb;
    }
    #pragma unroll 4
    for (int k = 0; k < 64; k++) {
        F4U wa, wb, x;
        wa.v = *(const float4*)(sWTd + k * PW + 8 * ty);
        wb.v = *(const float4*)(sWTd + k * PW + 8 * ty + 4);
        x.v  = *(const float4*)(sX + k * PX + 4 * tx);
        fma2(acc2[0][0], wa.u[0], x.u[0]); fma2(acc2[0][1], wa.u[0], x.u[1]);
        fma2(acc2[1][0], wa.u[1], x.u[0]); fma2(acc2[1][1], wa.u[1], x.u[1]);
        fma2(acc2[2][0], wb.u[0], x.u[0]); fma2(acc2[2][1], wb.u[0], x.u[1]);
        fma2(acc2[3][0], wb.u[1], x.u[0]); fma2(acc2[3][1], wb.u[1], x.u[1]);
    }
}

// channel-major store: dst[(4ty+i)*nstride + 4tx ..]
__device__ __forceinline__ void store_cmajor(float* __restrict__ dst, int nstride,
                                             u64 acc2[4][2], int tx, int ty)
{
    #pragma unroll
    for (int i = 0; i < 4; i++) {
        float2 a0 = unpk(acc2[i][0]), a1 = unpk(acc2[i][1]);
        *(float4*)(dst + (size_t)(4 * ty + i) * nstride + 4 * tx) =
            make_float4(a0.x, a0.y, a1.x, a1.y);
    }
}

// position-major store: dst[pos*64 + 4ty ..] (64 floats per position)
__device__ __forceinline__ void store_nmajor(float* __restrict__ dst,
                                             u64 acc2[4][2], int tx, int ty)
{
    float2 r[4][2];
    #pragma unroll
    for (int i = 0; i < 4; i++) {
        r[i][0] = unpk(acc2[i][0]); r[i][1] = unpk(acc2[i][1]);
    }
    #pragma unroll
    for (int jj = 0; jj < 4; jj++) {
        float v0 = (jj & 1) ? r[0][jj >> 1].y : r[0][jj >> 1].x;
        float v1 = (jj & 1) ? r[1][jj >> 1].y : r[1][jj >> 1].x;
        float v2 = (jj & 1) ? r[2][jj >> 1].y : r[2][jj >> 1].x;
        float v3 = (jj & 1) ? r[3][jj >> 1].y : r[3][jj >> 1].x;
        *(float4*)(dst + (size_t)(4 * tx + jj) * 64 + 4 * ty) =
            make_float4(v0, v1, v2, v3);
    }
}

// K, V, Q projections from x. gridDim.y: 0=K(c-major) 1=V(n-major) 2=Q(c-major).
__global__ __launch_bounds__(256, 2)
void projA_kernel(const float* __restrict__ x,
                  const float* __restrict__ wK, const float* __restrict__ bK,
                  const float* __restrict__ wV, const float* __restrict__ bV,
                  const float* __restrict__ wQ, const float* __restrict__ bQ)
{
    extern __shared__ float sh[];
    float* sWTd = sh;
    float* sX   = sh + 64 * PW;
    float* sb   = sX + 64 * PX;
    int which = blockIdx.y;
    int tid = threadIdx.x;
    const float* w  = which == 0 ? wK : (which == 1 ? wV : wQ);
    const float* bs = which == 0 ? bK : (which == 1 ? bV : bQ);
    load_w_dup(w, bs, sWTd, sb, tid);

    int gpos0 = blockIdx.x * 64;
    int b = gpos0 >> 12, n0 = gpos0 & (N_ - 1);
    const float* xb = x + (size_t)b * C_ * N_;
    for (int i = tid; i < 1024; i += 256) {
        int c = i >> 4, pg = (i & 15) * 4;
        *(float4*)(sX + c * PX + pg) = *(const float4*)(xb + (size_t)c * N_ + n0 + pg);
    }
    __syncthreads();

    int tx = tid & 15, ty = tid >> 4;
    u64 acc2[4][2];
    gemm_tile(sWTd, sX, sb, acc2, tx, ty);

    if (which == 0)      store_cmajor(g_K + (size_t)b * C_ * N_ + n0, N_, acc2, tx, ty);
    else if (which == 2) store_cmajor(g_Q + (size_t)b * C_ * N_ + n0, N_, acc2, tx, ty);
    else                 store_nmajor(g_V + (size_t)gpos0 * 64, acc2, tx, ty);
}

// Pooled q: qp = w_q @ avg_pool2(x) + b_q (pool commutes with 1x1 conv). c-major.
__global__ __launch_bounds__(256, 2)
void projP_kernel(const float* __restrict__ x,
                  const float* __restrict__ wq, const float* __restrict__ bq)
{
    extern __shared__ float sh[];
    float* sWTd = sh;
    float* sX   = sh + 64 * PW;
    float* sb   = sX + 64 * PX;
    int tid = threadIdx.x;
    load_w_dup(wq, bq, sWTd, sb, tid);

    int gpos0 = blockIdx.x * 64;
    int b = gpos0 >> 10, j0 = gpos0 & (N4_ - 1);
    const float* xb = x + (size_t)b * C_ * N_;
    for (int i = tid; i < 4096; i += 256) {
        int c = i >> 6, j = i & 63;
        int jj = j0 + j;
        int r = jj >> 5, col = jj & 31;
        const float* p = xb + (size_t)c * N_ + r * 128 + col * 2;
        float2 a = *(const float2*)p;
        float2 d = *(const float2*)(p + 64);
        sX[c * PX + j] = 0.25f * (a.x + a.y + d.x + d.y);
    }
    __syncthreads();

    int tx = tid & 15, ty = tid >> 4;
    u64 acc2[4][2];
    gemm_tile(sWTd, sX, sb, acc2, tx, ty);
    store_cmajor(g_qp + (size_t)b * C_ * N4_ + j0, N4_, acc2, tx, ty);
}

// kp (c-major), vp (n-major) from stage1 output. gridDim.y: 0=kp, 1=vp.
__global__ __launch_bounds__(256, 2)
void projC_kernel(const float* __restrict__ wk, const float* __restrict__ bk,
                  const float* __restrict__ wv, const float* __restrict__ bv)
{
    extern __shared__ float sh[];
    float* sWTd = sh;
    float* sX   = sh + 64 * PW;
    float* sb   = sX + 64 * PX;
    int which = blockIdx.y;
    int tid = threadIdx.x;
    load_w_dup(which ? wv : wk, which ? bv : bk, sWTd, sb, tid);

    int gpos0 = blockIdx.x * 64;
    int b = gpos0 >> 10, j0 = gpos0 & (N4_ - 1);
    const float* src = g_o1 + (size_t)gpos0 * 64;
    for (int i = tid; i < 1024; i += 256) {
        int pos = i >> 4, cg = (i & 15) * 4;
        float4 v = *(const float4*)(src + (size_t)pos * 64 + cg);
        sX[(cg + 0) * PX + pos] = v.x;
        sX[(cg + 1) * PX + pos] = v.y;
        sX[(cg + 2) * PX + pos] = v.z;
        sX[(cg + 3) * PX + pos] = v.w;
    }
    __syncthreads();

    int tx = tid & 15, ty = tid >> 4;
    u64 acc2[4][2];
    gemm_tile(sWTd, sX, sb, acc2, tx, ty);
    if (which == 0) store_cmajor(g_kp + (size_t)b * C_ * N4_ + j0, N4_, acc2, tx, ty);
    else            store_nmajor(g_vp + (size_t)gpos0 * 64, acc2, tx, ty);
}

// ================= Fused flash-attention (fp32x2, TQ=32 tiles) ==============
// 32-query tile per CTA, 256 threads as 16x16, thread = 2 q-rows x 4 keys.
// sQd: [d][2q] dup pairs (pitch PQ)    sK: [d][n]   sV: [n][c]  (pitch PQ)
// sPd: [q][2k] dup pairs (pitch PP), built in softmax.

template<bool FINAL>
__global__ __launch_bounds__(256, 2)
void attn_kernel(float* __restrict__ outg,
                 const float* __restrict__ xr,
                 const float* __restrict__ gp)
{
    constexpr int NKEY = FINAL ? 1024 : 4096;
    constexpr int NQ   = FINAL ? 4096 : 1024;
    constexpr int PQ = 68;
    constexpr int PP = 136;

    extern __shared__ float sh[];
    float* sQd = sh;                 // 64*68
    float* sK  = sQd + 64 * PQ;      // 64*68
    float* sV  = sK  + 64 * PQ;      // 64*68
    float* sPd = sV  + 64 * PQ;      // 32*136

    int tid = threadIdx.x;
    int tx = tid & 15, ty = tid >> 4;
    int b  = blockIdx.y;
    int qt = blockIdx.x;

    const float* Qb = (FINAL ? g_Q  : g_qp) + (size_t)b * C_ * NQ;
    const float* Kb = (FINAL ? g_kp : g_K ) + (size_t)b * C_ * NKEY;
    const float* Vb = (FINAL ? g_vp : g_V ) + (size_t)b * NKEY * C_;

    // Q tile (64d x 32q), duplicated pairs.
    for (int i = tid; i < 512; i += 256) {
        int row = i >> 3, dg = (i & 7) * 4;
        float4 v = *(const float4*)(Qb + (size_t)row * NQ + qt * 32 + dg);
        *(float4*)(sQd + row * PQ + 2 * dg)     = make_float4(v.x, v.x, v.y, v.y);
        *(float4*)(sQd + row * PQ + 2 * dg + 4) = make_float4(v.z, v.z, v.w, v.w);
    }

    float m[2], l[2];
    u64 acc2[2][2];
    #pragma unroll
    for (int i = 0; i < 2; i++) {
        m[i] = -1e30f; l[i] = 0.f;
        acc2[i][0] = 0ull; acc2[i][1] = 0ull;
    }
    __syncthreads();

    for (int kt = 0; kt < NKEY / 64; kt++) {
        for (int i = tid; i < 1024; i += 256) {
            int row = i >> 4, dg = (i & 15) * 4;
            *(float4*)(sK + row * PQ + dg) =
                *(const float4*)(Kb + (size_t)row * NKEY + kt * 64 + dg);
            *(float4*)(sV + row * PQ + dg) =
                *(const float4*)(Vb + ((size_t)kt * 64 + row) * 64 + dg);
        }
        __syncthreads();

        // S = Q^T K : per d-step 2x LDS.128 + 4 FFMA2 (no MOVs)
        u64 s2[2][2];
        s2[0][0] = 0ull; s2[0][1] = 0ull; s2[1][0] = 0ull; s2[1][1] = 0ull;

        #pragma unroll 4
        for (int d = 0; d < 64; d++) {
            F4U qa, k;
            qa.v = *(const float4*)(sQd + d * PQ + 4 * ty);
            k.v  = *(const float4*)(sK  + d * PQ + 4 * tx);
            fma2(s2[0][0], qa.u[0], k.u[0]); fma2(s2[0][1], qa.u[0], k.u[1]);
            fma2(s2[1][0], qa.u[1], k.u[0]); fma2(s2[1][1], qa.u[1], k.u[1]);
        }

        // Online softmax; write dup'd P tile.
        #pragma unroll
        for (int i = 0; i < 2; i++) {
            float2 a = unpk(s2[i][0]), c = unpk(s2[i][1]);
            float tm = fmaxf(fmaxf(a.x, a.y), fmaxf(c.x, c.y));
            tm = fmaxf(tm, __shfl_xor_sync(0xffffffffu, tm, 1));
            tm = fmaxf(tm, __shfl_xor_sync(0xffffffffu, tm, 2));
            tm = fmaxf(tm, __shfl_xor_sync(0xffffffffu, tm, 4));
            tm = fmaxf(tm, __shfl_xor_sync(0xffffffffu, tm, 8));
            float mn = fmaxf(m[i], tm);
            float alpha = __expf(m[i] - mn);
            float p0 = __expf(a.x - mn), p1 = __expf(a.y - mn);
            float p2 = __expf(c.x - mn), p3 = __expf(c.y - mn);
            float ps = p0 + p1 + p2 + p3;
            ps += __shfl_xor_sync(0xffffffffu, ps, 1);
            ps += __shfl_xor_sync(0xffffffffu, ps, 2);
            ps += __shfl_xor_sync(0xffffffffu, ps, 4);
            ps += __shfl_xor_sync(0xffffffffu, ps, 8);
            l[i] = l[i] * alpha + ps;
            m[i] = mn;
            u64 al2 = pack2(alpha, alpha);
            mul2(acc2[i][0], al2);
            mul2(acc2[i][1], al2);
            *(float4*)(sPd + (2*ty + i) * PP + 8*tx)     = make_float4(p0, p0, p1, p1);
            *(float4*)(sPd + (2*ty + i) * PP + 8*tx + 4) = make_float4(p2, p2, p3, p3);
        }
        __syncthreads();

        // O += P @ V : per 4-key chunk 8x LDS.128 + 16 FFMA2 (no MOVs)
        #pragma unroll 2
        for (int kk4 = 0; kk4 < 16; kk4++) {
            F4U pa[2], pb[2], vv[4];
            #pragma unroll
            for (int i = 0; i < 2; i++) {
                pa[i].v = *(const float4*)(sPd + (2*ty + i) * PP + 8*kk4);
                pb[i].v = *(const float4*)(sPd + (2*ty + i) * PP + 8*kk4 + 4);
            }
            #pragma unroll
            for (int t = 0; t < 4; t++)
                vv[t].v = *(const float4*)(sV + (4*kk4 + t) * PQ + 4*tx);
            #pragma unroll
            for (int i = 0; i < 2; i++) {
                fma2(acc2[i][0], pa[i].u[0], vv[0].u[0]); fma2(acc2[i][1], pa[i].u[0], vv[0].u[1]);
                fma2(acc2[i][0], pa[i].u[1], vv[1].u[0]); fma2(acc2[i][1], pa[i].u[1], vv[1].u[1]);
                fma2(acc2[i][0], pb[i].u[0], vv[2].u[0]); fma2(acc2[i][1], pb[i].u[0], vv[2].u[1]);
                fma2(acc2[i][0], pb[i].u[1], vv[3].u[0]); fma2(acc2[i][1], pb[i].u[1], vv[3].u[1]);
            }
        }
        __syncthreads();
    }

    if (!FINAL) {
        // Stage1: write (b, j, c) position-major float4.
        size_t base = ((size_t)b * N4_ + qt * 32) * 64;
        #pragma unroll
        for (int i = 0; i < 2; i++) {
            float inv = 1.f / l[i];
            float2 a = unpk(acc2[i][0]), c = unpk(acc2[i][1]);
            *(float4*)(g_o1 + base + (2*ty + i) * 64 + 4*tx) =
                make_float4(a.x * inv, a.y * inv, c.x * inv, c.y * inv);
        }
    } else {
        // Stage2: transpose via smem, fuse gamma*out2 + x, write (B,C,H,W).
        #pragma unroll
        for (int i = 0; i < 2; i++) {
            float inv = 1.f / l[i];
            float2 a = unpk(acc2[i][0]), c = unpk(acc2[i][1]);
            *(float4*)(sPd + (2*ty + i) * PP + 4*tx) =
                make_float4(a.x * inv, a.y * inv, c.x * inv, c.y * inv);
        }
        __syncthreads();
        float gamma = gp[0];
        int n0 = qt * 32;
        #pragma unroll 4
        for (int r2 = 0; r2 < 8; r2++) {
            int idx = r2 * 256 + tid;
            int c = idx >> 5, nl = idx & 31;
            size_t ga = ((size_t)b * 64 + c) * (size_t)N_ + n0 + nl;
            outg[ga] = gamma * sPd[nl * PP + c] + xr[ga];
        }
    }
}

// ---------------- Launch ----------------

extern "C" void kernel_launch(void* const* d_in, const int* in_sizes, int n_in,
                              void* d_out, int out_size)
{
    (void)in_sizes; (void)n_in; (void)out_size;
    const float* x     = (const float*)d_in[0];
    const float* w_q   = (const float*)d_in[1];
    const float* b_q   = (const float*)d_in[2];
    const float* w_K   = (const float*)d_in[3];
    const float* b_K   = (const float*)d_in[4];
    const float* w_V   = (const float*)d_in[5];
    const float* b_V   = (const float*)d_in[6];
    const float* w_Q   = (const float*)d_in[7];
    const float* b_Q   = (const float*)d_in[8];
    const float* w_k   = (const float*)d_in[9];
    const float* b_k   = (const float*)d_in[10];
    const float* w_v   = (const float*)d_in[11];
    const float* b_v   = (const float*)d_in[12];
    const float* gamma = (const float*)d_in[13];
    float* out = (float*)d_out;

    const int proj_smem = PROJ_SMEM_FLOATS * 4;               // 52480 B
    const int attn_smem = (3 * 64 * 68 + 32 * 136) * 4;       // 69632 B

    cudaFuncSetAttribute(projA_kernel, cudaFuncAttributeMaxDynamicSharedMemorySize, proj_smem);
    cudaFuncSetAttribute(projP_kernel, cudaFuncAttributeMaxDynamicSharedMemorySize, proj_smem);
    cudaFuncSetAttribute(projC_kernel, cudaFuncAttributeMaxDynamicSharedMemorySize, proj_smem);
    cudaFuncSetAttribute(attn_kernel<false>, cudaFuncAttributeMaxDynamicSharedMemorySize, attn_smem);
    cudaFuncSetAttribute(attn_kernel<true>,  cudaFuncAttributeMaxDynamicSharedMemorySize, attn_smem);

    // Projections for stage 1 + stage 2 queries.
    projA_kernel<<<dim3(B_*N_/64, 3), 256, proj_smem>>>(x, w_K, b_K, w_V, b_V, w_Q, b_Q);
    projP_kernel<<<dim3(B_*N4_/64), 256, proj_smem>>>(x, w_q, b_q);

    // Stage 1 attention: 1024 pooled queries vs 4096 keys (256 CTAs).
    attn_kernel<false><<<dim3(N4_/32, B_), 256, attn_smem>>>(nullptr, nullptr, nullptr);

    // Stage 2 projections from stage1 output.
    projC_kernel<<<dim3(B_*N4_/64, 2), 256, proj_smem>>>(w_k, b_k, w_v, b_v);

    // Stage 2 attention + residual epilogue (1024 CTAs).
    attn_kernel<true><<<dim3(N_/32, B_), 256, attn_smem>>>(out, x, gamma);
}

// round 8
// speedup vs baseline: 1.6458x; 1.6458x over previous
#include <cuda_runtime.h>
#include <cstddef>

#define B_  8
#define C_  64
#define N_  4096
#define N4_ 1024

// Scratch (static device globals).
__device__ float g_K [B_*C_*N_];   // (b,c,n)  keys   stage1, channel-major
__device__ float g_V [B_*N_*C_];   // (b,n,c)  values stage1, position-major
__device__ float g_Q [B_*C_*N_];   // (b,c,n)  queries stage2, channel-major
__device__ float g_qp[B_*C_*N4_];  // (b,c,j)  pooled queries stage1, channel-major
__device__ float g_o1[B_*N4_*C_];  // (b,j,c)  stage1 output, position-major
__device__ float g_kp[B_*C_*N4_];  // (b,c,j)  keys   stage2, channel-major
__device__ float g_vp[B_*N4_*C_];  // (b,j,c)  values stage2, position-major
// Split-K stage1 partials.
__device__ float g_po[2*B_*N4_*C_]; // [half][b][j][c] unnormalized acc
__device__ float g_m2[2*B_*N4_];
__device__ float g_l2[2*B_*N4_];

typedef unsigned long long u64;

__device__ __forceinline__ u64 pack2(float x, float y) {
    u64 r; asm("mov.b64 %0, {%1,%2};" : "=l"(r) : "f"(x), "f"(y)); return r;
}
__device__ __forceinline__ float2 unpk(u64 v) {
    float2 r; asm("mov.b64 {%0,%1}, %2;" : "=f"(r.x), "=f"(r.y) : "l"(v)); return r;
}
__device__ __forceinline__ void fma2(u64& d, u64 a, u64 b) {
    asm("fma.rn.f32x2 %0, %1, %2, %0;" : "+l"(d) : "l"(a), "l"(b));
}
__device__ __forceinline__ void mul2(u64& d, u64 a) {
    asm("mul.rn.f32x2 %0, %0, %1;" : "+l"(d) : "l"(a));
}

union F4U { float4 v; float f[4]; u64 u[2]; };

// ================= Projection GEMM (64x64 W @ 64x64 X tile) ================
#define PW 136
#define PX 68
#define PROJ_SMEM_FLOATS (64*PW + 64*PX + 64)

__device__ __forceinline__ void load_w_dup(const float* __restrict__ w,
                                           const float* __restrict__ bias,
                                           float* sWTd, float* sb, int tid)
{
    for (int i = tid; i < 4096; i += 256) {
        int o = i >> 6, c = i & 63;
        float v = w[i];
        sWTd[c * PW + 2 * o]     = v;
        sWTd[c * PW + 2 * o + 1] = v;
    }
    if (tid < 64) sb[tid] = bias[tid];
}

__device__ __forceinline__ void gemm_tile(const float* sWTd, const float* sX,
                                          const float* sb, u64 acc2[4][2],
                                          int tx, int ty)
{
    #pragma unroll
    for (int i = 0; i < 4; i++) {
        float b = sb[4 * ty + i];
        u64 bb = pack2(b, b);
        acc2[i][0] = bb; acc2[i][1] = bb;
    }
    #pragma unroll 4
    for (int k = 0; k < 64; k++) {
        F4U wa, wb, x;
        wa.v = *(const float4*)(sWTd + k * PW + 8 * ty);
        wb.v = *(const float4*)(sWTd + k * PW + 8 * ty + 4);
        x.v  = *(const float4*)(sX + k * PX + 4 * tx);
        fma2(acc2[0][0], wa.u[0], x.u[0]); fma2(acc2[0][1], wa.u[0], x.u[1]);
        fma2(acc2[1][0], wa.u[1], x.u[0]); fma2(acc2[1][1], wa.u[1], x.u[1]);
        fma2(acc2[2][0], wb.u[0], x.u[0]); fma2(acc2[2][1], wb.u[0], x.u[1]);
        fma2(acc2[3][0], wb.u[1], x.u[0]); fma2(acc2[3][1], wb.u[1], x.u[1]);
    }
}

__device__ __forceinline__ void store_cmajor(float* __restrict__ dst, int nstride,
                                             u64 acc2[4][2], int tx, int ty)
{
    #pragma unroll
    for (int i = 0; i < 4; i++) {
        float2 a0 = unpk(acc2[i][0]), a1 = unpk(acc2[i][1]);
        *(float4*)(dst + (size_t)(4 * ty + i) * nstride + 4 * tx) =
            make_float4(a0.x, a0.y, a1.x, a1.y);
    }
}

__device__ __forceinline__ void store_nmajor(float* __restrict__ dst,
                                             u64 acc2[4][2], int tx, int ty)
{
    float2 r[4][2];
    #pragma unroll
    for (int i = 0; i < 4; i++) {
        r[i][0] = unpk(acc2[i][0]); r[i][1] = unpk(acc2[i][1]);
    }
    #pragma unroll
    for (int jj = 0; jj < 4; jj++) {
        float v0 = (jj & 1) ? r[0][jj >> 1].y : r[0][jj >> 1].x;
        float v1 = (jj & 1) ? r[1][jj >> 1].y : r[1][jj >> 1].x;
        float v2 = (jj & 1) ? r[2][jj >> 1].y : r[2][jj >> 1].x;
        float v3 = (jj & 1) ? r[3][jj >> 1].y : r[3][jj >> 1].x;
        *(float4*)(dst + (size_t)(4 * tx + jj) * 64 + 4 * ty) =
            make_float4(v0, v1, v2, v3);
    }
}

__global__ __launch_bounds__(256, 2)
void projA_kernel(const float* __restrict__ x,
                  const float* __restrict__ wK, const float* __restrict__ bK,
                  const float* __restrict__ wV, const float* __restrict__ bV,
                  const float* __restrict__ wQ, const float* __restrict__ bQ)
{
    extern __shared__ float sh[];
    float* sWTd = sh;
    float* sX   = sh + 64 * PW;
    float* sb   = sX + 64 * PX;
    int which = blockIdx.y;
    int tid = threadIdx.x;
    const float* w  = which == 0 ? wK : (which == 1 ? wV : wQ);
    const float* bs = which == 0 ? bK : (which == 1 ? bV : bQ);
    load_w_dup(w, bs, sWTd, sb, tid);

    int gpos0 = blockIdx.x * 64;
    int b = gpos0 >> 12, n0 = gpos0 & (N_ - 1);
    const float* xb = x + (size_t)b * C_ * N_;
    for (int i = tid; i < 1024; i += 256) {
        int c = i >> 4, pg = (i & 15) * 4;
        *(float4*)(sX + c * PX + pg) = *(const float4*)(xb + (size_t)c * N_ + n0 + pg);
    }
    __syncthreads();

    int tx = tid & 15, ty = tid >> 4;
    u64 acc2[4][2];
    gemm_tile(sWTd, sX, sb, acc2, tx, ty);

    if (which == 0)      store_cmajor(g_K + (size_t)b * C_ * N_ + n0, N_, acc2, tx, ty);
    else if (which == 2) store_cmajor(g_Q + (size_t)b * C_ * N_ + n0, N_, acc2, tx, ty);
    else                 store_nmajor(g_V + (size_t)gpos0 * 64, acc2, tx, ty);
}

__global__ __launch_bounds__(256, 2)
void projP_kernel(const float* __restrict__ x,
                  const float* __restrict__ wq, const float* __restrict__ bq)
{
    extern __shared__ float sh[];
    float* sWTd = sh;
    float* sX   = sh + 64 * PW;
    float* sb   = sX + 64 * PX;
    int tid = threadIdx.x;
    load_w_dup(wq, bq, sWTd, sb, tid);

    int gpos0 = blockIdx.x * 64;
    int b = gpos0 >> 10, j0 = gpos0 & (N4_ - 1);
    const float* xb = x + (size_t)b * C_ * N_;
    for (int i = tid; i < 4096; i += 256) {
        int c = i >> 6, j = i & 63;
        int jj = j0 + j;
        int r = jj >> 5, col = jj & 31;
        const float* p = xb + (size_t)c * N_ + r * 128 + col * 2;
        float2 a = *(const float2*)p;
        float2 d = *(const float2*)(p + 64);
        sX[c * PX + j] = 0.25f * (a.x + a.y + d.x + d.y);
    }
    __syncthreads();

    int tx = tid & 15, ty = tid >> 4;
    u64 acc2[4][2];
    gemm_tile(sWTd, sX, sb, acc2, tx, ty);
    store_cmajor(g_qp + (size_t)b * C_ * N4_ + j0, N4_, acc2, tx, ty);
}

__global__ __launch_bounds__(256, 2)
void projC_kernel(const float* __restrict__ wk, const float* __restrict__ bk,
                  const float* __restrict__ wv, const float* __restrict__ bv)
{
    extern __shared__ float sh[];
    float* sWTd = sh;
    float* sX   = sh + 64 * PW;
    float* sb   = sX + 64 * PX;
    int which = blockIdx.y;
    int tid = threadIdx.x;
    load_w_dup(which ? wv : wk, which ? bv : bk, sWTd, sb, tid);

    int gpos0 = blockIdx.x * 64;
    int b = gpos0 >> 10, j0 = gpos0 & (N4_ - 1);
    const float* src = g_o1 + (size_t)gpos0 * 64;
    for (int i = tid; i < 1024; i += 256) {
        int pos = i >> 4, cg = (i & 15) * 4;
        float4 v = *(const float4*)(src + (size_t)pos * 64 + cg);
        sX[(cg + 0) * PX + pos] = v.x;
        sX[(cg + 1) * PX + pos] = v.y;
        sX[(cg + 2) * PX + pos] = v.z;
        sX[(cg + 3) * PX + pos] = v.w;
    }
    __syncthreads();

    int tx = tid & 15, ty = tid >> 4;
    u64 acc2[4][2];
    gemm_tile(sWTd, sX, sb, acc2, tx, ty);
    if (which == 0) store_cmajor(g_kp + (size_t)b * C_ * N4_ + j0, N4_, acc2, tx, ty);
    else            store_nmajor(g_vp + (size_t)gpos0 * 64, acc2, tx, ty);
}

// ================= Fused flash-attention (R5 core, fp32x2) ==================
// 64-query tile per CTA, 256 threads as 16x16, 4x4 per thread; pairs packed
// along key/channel axis. sQ[d][q], sK[d][n], sV[n][c], sP[q][k], pitch 68.
// FINAL=false: split-K stage1 (blockIdx.z = key half) -> g_po/g_m2/g_l2.
// FINAL=true : stage2 + residual epilogue -> d_out.

template<bool FINAL>
__global__ __launch_bounds__(256, 2)
void attn_kernel(float* __restrict__ outg,
                 const float* __restrict__ xr,
                 const float* __restrict__ gp)
{
    constexpr int NKEY = FINAL ? 1024 : 4096;
    constexpr int NQ   = FINAL ? 4096 : 1024;
    constexpr int W = 68;

    extern __shared__ float sh[];
    float* sQ = sh;
    float* sK = sQ + 64*W;
    float* sV = sK + 64*W;
    float* sP = sV + 64*W;

    int tid = threadIdx.x;
    int tx = tid & 15, ty = tid >> 4;
    int b  = blockIdx.y;
    int qt = blockIdx.x;
    int half = FINAL ? 0 : blockIdx.z;

    const float* Qb = (FINAL ? g_Q  : g_qp) + (size_t)b * C_ * NQ;
    const float* Kb = (FINAL ? g_kp : g_K ) + (size_t)b * C_ * NKEY;
    const float* Vb = (FINAL ? g_vp : g_V ) + (size_t)b * NKEY * C_;

    for (int i = tid; i < 1024; i += 256) {
        int row = i >> 4, dg = (i & 15) * 4;
        *(float4*)(sQ + row * W + dg) =
            *(const float4*)(Qb + (size_t)row * NQ + qt * 64 + dg);
    }

    float m[4], l[4];
    u64 acc2[4][2];
    #pragma unroll
    for (int i = 0; i < 4; i++) {
        m[i] = -1e30f; l[i] = 0.f;
        acc2[i][0] = 0ull; acc2[i][1] = 0ull;
    }
    __syncthreads();

    int kt0 = FINAL ? 0 : half * (NKEY / 128);
    int kt1 = FINAL ? NKEY / 64 : kt0 + (NKEY / 128);
    for (int kt = kt0; kt < kt1; kt++) {
        for (int i = tid; i < 1024; i += 256) {
            int row = i >> 4, dg = (i & 15) * 4;
            *(float4*)(sK + row * W + dg) =
                *(const float4*)(Kb + (size_t)row * NKEY + kt * 64 + dg);
            *(float4*)(sV + row * W + dg) =
                *(const float4*)(Vb + ((size_t)kt * 64 + row) * 64 + dg);
        }
        __syncthreads();

        u64 s2[4][2];
        #pragma unroll
        for (int i = 0; i < 4; i++) { s2[i][0] = 0ull; s2[i][1] = 0ull; }

        #pragma unroll 4
        for (int d = 0; d < 64; d++) {
            F4U q, k;
            q.v = *(const float4*)(sQ + d * W + 4 * ty);
            k.v = *(const float4*)(sK + d * W + 4 * tx);
            #pragma unroll
            for (int i = 0; i < 4; i++) {
                u64 qq = pack2(q.f[i], q.f[i]);
                fma2(s2[i][0], qq, k.u[0]);
                fma2(s2[i][1], qq, k.u[1]);
            }
        }

        #pragma unroll
        for (int i = 0; i < 4; i++) {
            float2 a = unpk(s2[i][0]), c = unpk(s2[i][1]);
            float tm = fmaxf(fmaxf(a.x, a.y), fmaxf(c.x, c.y));
            tm = fmaxf(tm, __shfl_xor_sync(0xffffffffu, tm, 1));
            tm = fmaxf(tm, __shfl_xor_sync(0xffffffffu, tm, 2));
            tm = fmaxf(tm, __shfl_xor_sync(0xffffffffu, tm, 4));
            tm = fmaxf(tm, __shfl_xor_sync(0xffffffffu, tm, 8));
            float mn = fmaxf(m[i], tm);
            float alpha = __expf(m[i] - mn);
            float p0 = __expf(a.x - mn), p1 = __expf(a.y - mn);
            float p2 = __expf(c.x - mn), p3 = __expf(c.y - mn);
            float ps = p0 + p1 + p2 + p3;
            ps += __shfl_xor_sync(0xffffffffu, ps, 1);
            ps += __shfl_xor_sync(0xffffffffu, ps, 2);
            ps += __shfl_xor_sync(0xffffffffu, ps, 4);
            ps += __shfl_xor_sync(0xffffffffu, ps, 8);
            l[i] = l[i] * alpha + ps;
            m[i] = mn;
            u64 al2 = pack2(alpha, alpha);
            mul2(acc2[i][0], al2);
            mul2(acc2[i][1], al2);
            *(float4*)(sP + (4*ty + i) * W + 4*tx) = make_float4(p0, p1, p2, p3);
        }
        __syncthreads();

        #pragma unroll 2
        for (int kk4 = 0; kk4 < 16; kk4++) {
            F4U p[4], vv[4];
            #pragma unroll
            for (int i = 0; i < 4; i++)
                p[i].v = *(const float4*)(sP + (4*ty + i) * W + 4*kk4);
            #pragma unroll
            for (int t = 0; t < 4; t++)
                vv[t].v = *(const float4*)(sV + (4*kk4 + t) * W + 4*tx);
            #pragma unroll
            for (int i = 0; i < 4; i++) {
                #pragma unroll
                for (int t = 0; t < 4; t++) {
                    u64 pb = pack2(p[i].f[t], p[i].f[t]);
                    fma2(acc2[i][0], pb, vv[t].u[0]);
                    fma2(acc2[i][1], pb, vv[t].u[1]);
                }
            }
        }
        __syncthreads();
    }

    if (!FINAL) {
        // Split-K partial: unnormalized acc + (m,l) per row.
        size_t base = ((size_t)(half * B_ + b) * N4_ + qt * 64) * 64;
        #pragma unroll
        for (int i = 0; i < 4; i++) {
            float2 a = unpk(acc2[i][0]), c = unpk(acc2[i][1]);
            *(float4*)(g_po + base + (4*ty + i) * 64 + 4*tx) =
                make_float4(a.x, a.y, c.x, c.y);
        }
        if (tx == 0) {
            int r = (half * B_ + b) * N4_ + qt * 64 + 4 * ty;
            #pragma unroll
            for (int i = 0; i < 4; i++) { g_m2[r + i] = m[i]; g_l2[r + i] = l[i]; }
        }
    } else {
        #pragma unroll
        for (int i = 0; i < 4; i++) {
            float inv = 1.f / l[i];
            float2 a = unpk(acc2[i][0]), c = unpk(acc2[i][1]);
            *(float4*)(sP + (4*ty + i) * W + 4*tx) =
                make_float4(a.x * inv, a.y * inv, c.x * inv, c.y * inv);
        }
        __syncthreads();
        float gamma = gp[0];
        int n0 = qt * 64;
        #pragma unroll 4
        for (int r2 = 0; r2 < 16; r2++) {
            int idx = r2 * 256 + tid;
            int c = idx >> 6, nl = idx & 63;
            size_t ga = ((size_t)b * 64 + c) * (size_t)N_ + n0 + nl;
            outg[ga] = gamma * sP[nl * W + c] + xr[ga];
        }
    }
}

// Merge the two split-K partials: exact flash combine.
__global__ __launch_bounds__(256)
void combine_kernel()
{
    int idx = blockIdx.x * 256 + threadIdx.x;   // over 8192*16 float4 groups
    int row = idx >> 4, c4 = (idx & 15) * 4;
    float m0 = g_m2[row], m1 = g_m2[B_*N4_ + row];
    float l0 = g_l2[row], l1 = g_l2[B_*N4_ + row];
    float M = fmaxf(m0, m1);
    float w0 = __expf(m0 - M), w1 = __expf(m1 - M);
    float inv = 1.f / (l0 * w0 + l1 * w1);
    float4 a0 = *(const float4*)(g_po + (size_t)row * 64 + c4);
    float4 a1 = *(const float4*)(g_po + (size_t)(B_*N4_ + row) * 64 + c4);
    *(float4*)(g_o1 + (size_t)row * 64 + c4) = make_float4(
        (a0.x * w0 + a1.x * w1) * inv,
        (a0.y * w0 + a1.y * w1) * inv,
        (a0.z * w0 + a1.z * w1) * inv,
        (a0.w * w0 + a1.w * w1) * inv);
}

// ---------------- Launch ----------------

extern "C" void kernel_launch(void* const* d_in, const int* in_sizes, int n_in,
                              void* d_out, int out_size)
{
    (void)in_sizes; (void)n_in; (void)out_size;
    const float* x     = (const float*)d_in[0];
    const float* w_q   = (const float*)d_in[1];
    const float* b_q   = (const float*)d_in[2];
    const float* w_K   = (const float*)d_in[3];
    const float* b_K   = (const float*)d_in[4];
    const float* w_V   = (const float*)d_in[5];
    const float* b_V   = (const float*)d_in[6];
    const float* w_Q   = (const float*)d_in[7];
    const float* b_Q   = (const float*)d_in[8];
    const float* w_k   = (const float*)d_in[9];
    const float* b_k   = (const float*)d_in[10];
    const float* w_v   = (const float*)d_in[11];
    const float* b_v   = (const float*)d_in[12];
    const float* gamma = (const float*)d_in[13];
    float* out = (float*)d_out;

    const int proj_smem = PROJ_SMEM_FLOATS * 4;   // 52480 B
    const int attn_smem = 4 * 64 * 68 * 4;        // 69632 B

    cudaFuncSetAttribute(projA_kernel, cudaFuncAttributeMaxDynamicSharedMemorySize, proj_smem);
    cudaFuncSetAttribute(projP_kernel, cudaFuncAttributeMaxDynamicSharedMemorySize, proj_smem);
    cudaFuncSetAttribute(projC_kernel, cudaFuncAttributeMaxDynamicSharedMemorySize, proj_smem);
    cudaFuncSetAttribute(attn_kernel<false>, cudaFuncAttributeMaxDynamicSharedMemorySize, attn_smem);
    cudaFuncSetAttribute(attn_kernel<true>,  cudaFuncAttributeMaxDynamicSharedMemorySize, attn_smem);

    // Projections for stage 1 + stage 2 queries.
    projA_kernel<<<dim3(B_*N_/64, 3), 256, proj_smem>>>(x, w_K, b_K, w_V, b_V, w_Q, b_Q);
    projP_kernel<<<dim3(B_*N4_/64), 256, proj_smem>>>(x, w_q, b_q);

    // Stage 1 attention: split-K over 2 halves (256 CTAs), then combine.
    attn_kernel<false><<<dim3(N4_/64, B_, 2), 256, attn_smem>>>(nullptr, nullptr, nullptr);
    combine_kernel<<<(B_*N4_*16)/256, 256>>>();

    // Stage 2 projections from stage1 output.
    projC_kernel<<<dim3(B_*N4_/64, 2), 256, proj_smem>>>(w_k, b_k, w_v, b_v);

    // Stage 2 attention + residual epilogue (512 CTAs).
    attn_kernel<true><<<dim3(N_/64, B_), 256, attn_smem>>>(out, x, gamma);
}